// round 2
// baseline (speedup 1.0000x reference)
#include <cuda_runtime.h>

// TriangleLinear: out[b, 8191-r] = bias[r] + sum_{c >= max(0, r-4)} W_packed[off(r) + c - s(r)] * x[b, c]
// Packed row offset: off(r) = r*8192 - tri(r), tri(r) = (r-5)(r-4)/2 for r>=5 else 0.
//
// Decomposition: warp gw owns rows {t, t+1, 8190-t, 8191-t}, t = 2*gw.
// cnt(r) + cnt(8191-r) = const  =>  uniform work per warp, no atomics.
// Each lane register-blocks 4 rows x 8 batches (32 accumulators); lanes stride
// columns (c + lane + 32j, j<4) so weight and x loads are fully coalesced.
// Phase 1 runs only the two low-start rows; phase 2 runs all four.

constexpr int N = 8192;
constexpr int BATCH = 8;

__global__ __launch_bounds__(128)
void tri_linear_kernel(const float* __restrict__ x,
                       const float* __restrict__ w,
                       const float* __restrict__ bias,
                       float* __restrict__ out)
{
    const int lane = threadIdx.x & 31;
    const int wid  = threadIdx.x >> 5;
    const int gw   = blockIdx.x * 4 + wid;   // 0 .. 2047
    const int t    = gw * 2;

    int r[4];
    r[0] = t; r[1] = t + 1; r[2] = 8190 - t; r[3] = 8191 - t;

    int s[4], wb[4];
#pragma unroll
    for (int i = 0; i < 4; i++) {
        const int ri = r[i];
        s[i] = (ri - 4 > 0) ? (ri - 4) : 0;
        const int tri = (ri >= 5) ? ((ri - 5) * (ri - 4)) / 2 : 0;
        wb[i] = ri * N - tri - s[i];         // weight index of column c is wb[i] + c
    }

    float acc[4][BATCH];
#pragma unroll
    for (int i = 0; i < 4; i++)
#pragma unroll
        for (int b = 0; b < BATCH; b++) acc[i][b] = 0.0f;

    const int c0   = s[0] & ~127;            // aligned start for the top rows
    const int cmid = s[2] & ~127;            // aligned start for the bottom rows

    // ---------- Phase 1: only rows 0,1 active ----------
    for (int c = c0; c < cmid; c += 128) {
        float xv[BATCH][4];
#pragma unroll
        for (int b = 0; b < BATCH; b++)
#pragma unroll
            for (int j = 0; j < 4; j++)
                xv[b][j] = __ldg(x + b * N + c + lane + 32 * j);

#pragma unroll
        for (int i = 0; i < 2; i++) {
#pragma unroll
            for (int j = 0; j < 4; j++) {
                const int col = c + lane + 32 * j;
                // guard only matters on the first step; address is always in-bounds
                const float wv = (col >= s[i]) ? __ldcs(w + wb[i] + col) : 0.0f;
#pragma unroll
                for (int b = 0; b < BATCH; b++)
                    acc[i][b] = fmaf(wv, xv[b][j], acc[i][b]);
            }
        }
    }

    // ---------- Phase 2: all four rows active ----------
    for (int c = cmid; c < N; c += 128) {
        float xv[BATCH][4];
#pragma unroll
        for (int b = 0; b < BATCH; b++)
#pragma unroll
            for (int j = 0; j < 4; j++)
                xv[b][j] = __ldg(x + b * N + c + lane + 32 * j);

#pragma unroll
        for (int i = 0; i < 4; i++) {
#pragma unroll
            for (int j = 0; j < 4; j++) {
                const int col = c + lane + 32 * j;
                const float wv = (col >= s[i]) ? __ldcs(w + wb[i] + col) : 0.0f;
#pragma unroll
                for (int b = 0; b < BATCH; b++)
                    acc[i][b] = fmaf(wv, xv[b][j], acc[i][b]);
            }
        }
    }

    // ---------- Reduce across lanes, add bias, store flipped ----------
#pragma unroll
    for (int i = 0; i < 4; i++) {
        const float bi = __ldg(bias + r[i]);
#pragma unroll
        for (int b = 0; b < BATCH; b++) {
            float v = acc[i][b];
            v += __shfl_xor_sync(0xffffffffu, v, 16);
            v += __shfl_xor_sync(0xffffffffu, v, 8);
            v += __shfl_xor_sync(0xffffffffu, v, 4);
            v += __shfl_xor_sync(0xffffffffu, v, 2);
            v += __shfl_xor_sync(0xffffffffu, v, 1);
            if (lane == b)
                out[b * N + (N - 1 - r[i])] = v + bi;
        }
    }
}

extern "C" void kernel_launch(void* const* d_in, const int* in_sizes, int n_in,
                              void* d_out, int out_size)
{
    const float* x    = (const float*)d_in[0];   // [8, 8192] fp32
    const float* w    = (const float*)d_in[1];   // packed weights, 33,591,286 fp32
    const float* bias = (const float*)d_in[2];   // [8192] fp32
    float* out        = (float*)d_out;           // [8, 8192] fp32

    // 2048 warps total -> 512 blocks x 128 threads (uniform work per warp)
    tri_linear_kernel<<<512, 128>>>(x, w, bias, out);
}

// round 3
// speedup vs baseline: 1.0102x; 1.0102x over previous
#include <cuda_runtime.h>

// TriangleLinear: out[b, 8191-r] = bias[r] + sum_{c >= max(0, r-4)} W_packed[off(r) + c - s(r)] * x[b, c]
// Packed row offset: off(r) = r*8192 - tri(r), tri(r) = (r-5)(r-4)/2 for r>=5 else 0.
//
// Decomposition: warp gw owns rows {t, t+1, 8190-t, 8191-t}, t = 2*gw.
// cnt(r) + cnt(8191-r) = const  =>  uniform work per warp, no atomics.
// Each lane register-blocks 4 rows x 8 batches (32 accumulators); lanes stride
// columns (c + lane + 32j, j<4) so weight and x loads are fully coalesced.
// Phase 1 runs only the two low-start rows; phase 2 runs all four.

constexpr int N = 8192;
constexpr int BATCH = 8;

__global__ __launch_bounds__(128)
void tri_linear_kernel(const float* __restrict__ x,
                       const float* __restrict__ w,
                       const float* __restrict__ bias,
                       float* __restrict__ out)
{
    const int lane = threadIdx.x & 31;
    const int wid  = threadIdx.x >> 5;
    const int gw   = blockIdx.x * 4 + wid;   // 0 .. 2047
    const int t    = gw * 2;

    int r[4];
    r[0] = t; r[1] = t + 1; r[2] = 8190 - t; r[3] = 8191 - t;

    int s[4], wb[4];
#pragma unroll
    for (int i = 0; i < 4; i++) {
        const int ri = r[i];
        s[i] = (ri - 4 > 0) ? (ri - 4) : 0;
        const int tri = (ri >= 5) ? ((ri - 5) * (ri - 4)) / 2 : 0;
        wb[i] = ri * N - tri - s[i];         // weight index of column c is wb[i] + c
    }

    float acc[4][BATCH];
#pragma unroll
    for (int i = 0; i < 4; i++)
#pragma unroll
        for (int b = 0; b < BATCH; b++) acc[i][b] = 0.0f;

    const int c0   = s[0] & ~127;            // aligned start for the top rows
    const int cmid = s[2] & ~127;            // aligned start for the bottom rows

    // ---------- Phase 1: only rows 0,1 active ----------
    for (int c = c0; c < cmid; c += 128) {
        float xv[BATCH][4];
#pragma unroll
        for (int b = 0; b < BATCH; b++)
#pragma unroll
            for (int j = 0; j < 4; j++)
                xv[b][j] = __ldg(x + b * N + c + lane + 32 * j);

#pragma unroll
        for (int i = 0; i < 2; i++) {
#pragma unroll
            for (int j = 0; j < 4; j++) {
                const int col = c + lane + 32 * j;
                // guard only matters on the first step; address is always in-bounds
                const float wv = (col >= s[i]) ? __ldcs(w + wb[i] + col) : 0.0f;
#pragma unroll
                for (int b = 0; b < BATCH; b++)
                    acc[i][b] = fmaf(wv, xv[b][j], acc[i][b]);
            }
        }
    }

    // ---------- Phase 2: all four rows active ----------
    for (int c = cmid; c < N; c += 128) {
        float xv[BATCH][4];
#pragma unroll
        for (int b = 0; b < BATCH; b++)
#pragma unroll
            for (int j = 0; j < 4; j++)
                xv[b][j] = __ldg(x + b * N + c + lane + 32 * j);

#pragma unroll
        for (int i = 0; i < 4; i++) {
#pragma unroll
            for (int j = 0; j < 4; j++) {
                const int col = c + lane + 32 * j;
                const float wv = (col >= s[i]) ? __ldcs(w + wb[i] + col) : 0.0f;
#pragma unroll
                for (int b = 0; b < BATCH; b++)
                    acc[i][b] = fmaf(wv, xv[b][j], acc[i][b]);
            }
        }
    }

    // ---------- Reduce across lanes, add bias, store flipped ----------
#pragma unroll
    for (int i = 0; i < 4; i++) {
        const float bi = __ldg(bias + r[i]);
#pragma unroll
        for (int b = 0; b < BATCH; b++) {
            float v = acc[i][b];
            v += __shfl_xor_sync(0xffffffffu, v, 16);
            v += __shfl_xor_sync(0xffffffffu, v, 8);
            v += __shfl_xor_sync(0xffffffffu, v, 4);
            v += __shfl_xor_sync(0xffffffffu, v, 2);
            v += __shfl_xor_sync(0xffffffffu, v, 1);
            if (lane == b)
                out[b * N + (N - 1 - r[i])] = v + bi;
        }
    }
}

extern "C" void kernel_launch(void* const* d_in, const int* in_sizes, int n_in,
                              void* d_out, int out_size)
{
    const float* x    = (const float*)d_in[0];   // [8, 8192] fp32
    const float* w    = (const float*)d_in[1];   // packed weights, 33,591,286 fp32
    const float* bias = (const float*)d_in[2];   // [8192] fp32
    float* out        = (float*)d_out;           // [8, 8192] fp32

    // 2048 warps total -> 512 blocks x 128 threads (uniform work per warp)
    tri_linear_kernel<<<512, 128>>>(x, w, bias, out);
}

// round 4
// speedup vs baseline: 1.8045x; 1.7863x over previous
#include <cuda_runtime.h>

// TriangleLinear on GB300.
// out[b, 8191-r] = bias[r] + sum_{c >= max(0, r-4)} W[off(r) + c - s(r)] * x[b, c]
// off(r) = r*8192 - tri(r), tri(r) = (r-5)(r-4)/2 for r>=5 else 0.
//
// Round-3 scheme:
//  - kernel 1: transpose x -> xT[col][b] (batch contiguous, 16B aligned)
//  - kernel 2: warp gw handles row pair p = gw>>1 (rows p and 8191-p) over the
//    column 128-blocks whose index parity == (gw & 1).  cnt(p)+cnt(8191-p) is
//    constant and the parity split halves it evenly => ~4100 weights per warp,
//    8192 perfectly uniform warps (2048 blocks).  Partials (lane-reduced) go to
//    g_partial[half][b][flipped col].
//  - kernel 3: out = partial[0] + partial[1] + bias (flip folded). Deterministic.

constexpr int N = 8192;
constexpr int BATCH = 8;

__device__ __align__(16) float g_xT[N * BATCH];        // xT[col*8 + b]
__device__ float g_partial[2][BATCH][N];               // [half][b][flipped col]

// ---------------- kernel 1: x transpose ----------------
__global__ void transpose_x_kernel(const float* __restrict__ x)
{
    const int idx = blockIdx.x * blockDim.x + threadIdx.x;   // 0 .. 65535
    const int col = idx >> 3;
    const int b   = idx & 7;
    g_xT[idx] = __ldg(x + b * N + col);
}

// ---------------- kernel 2: main triangular matvec ----------------
__global__ __launch_bounds__(128, 7)
void tri_main_kernel(const float* __restrict__ w)
{
    const int lane = threadIdx.x & 31;
    const int wid  = threadIdx.x >> 5;
    const int gw   = blockIdx.x * 4 + wid;      // 0 .. 8191
    const int p    = gw >> 1;                   // pair 0 .. 4095
    const int h    = gw & 1;                    // column-block parity

    const int rt = p;                           // top row (long)
    const int rb = N - 1 - p;                   // bottom row (short)
    const int st = (p - 4 > 0) ? (p - 4) : 0;   // first active col, top
    const int sb = rb - 4;                      // first active col, bottom (>= 4092)

    // packed-weight base: index of column c in row r is  wb + c
    const int trit = (rt >= 5) ? ((rt - 5) * (rt - 4)) / 2 : 0;
    const int trib = ((rb - 5) * (rb - 4)) / 2;           // rb >= 4096 always
    const int wbt  = rt * N - trit - st;
    const int wbb  = rb * N - trib - sb;

    const int kg_t = st >> 7;                   // first 128-block touching top row
    const int kg_b = sb >> 7;                   // first 128-block touching bottom row

    float acc_t[BATCH], acc_b[BATCH];
#pragma unroll
    for (int b = 0; b < BATCH; b++) { acc_t[b] = 0.0f; acc_b[b] = 0.0f; }

    // first block of parity h that is >= kg_t / >= kg_b
    int k1 = kg_t + (((kg_t & 1) != h) ? 1 : 0);
    int k2 = kg_b + (((kg_b & 1) != h) ? 1 : 0);

    // ---------- Phase 1: top row only, blocks [k1, kg_b) with parity h ----------
    for (int k = k1; k < kg_b; k += 2) {
        const int c = k << 7;
        float4 xlo[4], xhi[4];
#pragma unroll
        for (int j = 0; j < 4; j++) {
            const int col = c + lane + 32 * j;
            const float4* xp = (const float4*)(g_xT + col * BATCH);
            xlo[j] = __ldg(xp);
            xhi[j] = __ldg(xp + 1);
        }
#pragma unroll
        for (int j = 0; j < 4; j++) {
            const int col = c + lane + 32 * j;
            const float wv = (col >= st) ? __ldcs(w + wbt + col) : 0.0f;
            acc_t[0] = fmaf(wv, xlo[j].x, acc_t[0]);
            acc_t[1] = fmaf(wv, xlo[j].y, acc_t[1]);
            acc_t[2] = fmaf(wv, xlo[j].z, acc_t[2]);
            acc_t[3] = fmaf(wv, xlo[j].w, acc_t[3]);
            acc_t[4] = fmaf(wv, xhi[j].x, acc_t[4]);
            acc_t[5] = fmaf(wv, xhi[j].y, acc_t[5]);
            acc_t[6] = fmaf(wv, xhi[j].z, acc_t[6]);
            acc_t[7] = fmaf(wv, xhi[j].w, acc_t[7]);
        }
    }

    // ---------- Phase 2: both rows, blocks [k2, 64) with parity h ----------
    for (int k = k2; k < 64; k += 2) {
        const int c = k << 7;
        float4 xlo[4], xhi[4];
#pragma unroll
        for (int j = 0; j < 4; j++) {
            const int col = c + lane + 32 * j;
            const float4* xp = (const float4*)(g_xT + col * BATCH);
            xlo[j] = __ldg(xp);
            xhi[j] = __ldg(xp + 1);
        }
#pragma unroll
        for (int j = 0; j < 4; j++) {
            const int col = c + lane + 32 * j;
            const float wt = (col >= st) ? __ldcs(w + wbt + col) : 0.0f;
            const float wb = (col >= sb) ? __ldcs(w + wbb + col) : 0.0f;
            acc_t[0] = fmaf(wt, xlo[j].x, acc_t[0]);
            acc_b[0] = fmaf(wb, xlo[j].x, acc_b[0]);
            acc_t[1] = fmaf(wt, xlo[j].y, acc_t[1]);
            acc_b[1] = fmaf(wb, xlo[j].y, acc_b[1]);
            acc_t[2] = fmaf(wt, xlo[j].z, acc_t[2]);
            acc_b[2] = fmaf(wb, xlo[j].z, acc_b[2]);
            acc_t[3] = fmaf(wt, xlo[j].w, acc_t[3]);
            acc_b[3] = fmaf(wb, xlo[j].w, acc_b[3]);
            acc_t[4] = fmaf(wt, xhi[j].x, acc_t[4]);
            acc_b[4] = fmaf(wb, xhi[j].x, acc_b[4]);
            acc_t[5] = fmaf(wt, xhi[j].y, acc_t[5]);
            acc_b[5] = fmaf(wb, xhi[j].y, acc_b[5]);
            acc_t[6] = fmaf(wt, xhi[j].z, acc_t[6]);
            acc_b[6] = fmaf(wb, xhi[j].z, acc_b[6]);
            acc_t[7] = fmaf(wt, xhi[j].w, acc_t[7]);
            acc_b[7] = fmaf(wb, xhi[j].w, acc_b[7]);
        }
    }

    // ---------- lane-reduce and store partials (pre-flipped) ----------
#pragma unroll
    for (int b = 0; b < BATCH; b++) {
        float vt = acc_t[b];
        float vb = acc_b[b];
        vt += __shfl_xor_sync(0xffffffffu, vt, 16);
        vb += __shfl_xor_sync(0xffffffffu, vb, 16);
        vt += __shfl_xor_sync(0xffffffffu, vt, 8);
        vb += __shfl_xor_sync(0xffffffffu, vb, 8);
        vt += __shfl_xor_sync(0xffffffffu, vt, 4);
        vb += __shfl_xor_sync(0xffffffffu, vb, 4);
        vt += __shfl_xor_sync(0xffffffffu, vt, 2);
        vb += __shfl_xor_sync(0xffffffffu, vb, 2);
        vt += __shfl_xor_sync(0xffffffffu, vt, 1);
        vb += __shfl_xor_sync(0xffffffffu, vb, 1);
        if (lane == b) {
            g_partial[h][b][N - 1 - rt] = vt;
            g_partial[h][b][N - 1 - rb] = vb;
        }
    }
}

// ---------------- kernel 3: combine halves + bias (flip folded) ----------------
__global__ void reduce_out_kernel(const float* __restrict__ bias,
                                  float* __restrict__ out)
{
    const int idx = blockIdx.x * blockDim.x + threadIdx.x;   // 0 .. 65535
    const int b = idx >> 13;         // / 8192
    const int j = idx & (N - 1);     // flipped output column
    out[idx] = g_partial[0][b][j] + g_partial[1][b][j] + __ldg(bias + (N - 1 - j));
}

extern "C" void kernel_launch(void* const* d_in, const int* in_sizes, int n_in,
                              void* d_out, int out_size)
{
    const float* x    = (const float*)d_in[0];   // [8, 8192] fp32
    const float* w    = (const float*)d_in[1];   // packed weights fp32
    const float* bias = (const float*)d_in[2];   // [8192] fp32
    float* out        = (float*)d_out;           // [8, 8192] fp32

    transpose_x_kernel<<<64, 1024>>>(x);
    tri_main_kernel<<<2048, 128>>>(w);           // 8192 uniform warps
    reduce_out_kernel<<<64, 1024>>>(bias, out);
}

// round 5
// speedup vs baseline: 2.0916x; 1.1591x over previous
#include <cuda_runtime.h>

// TriangleLinear on GB300 (sm_103a).
// out[b, 8191-r] = bias[r] + sum_{c >= s(r)} W[wb(r) + c] * x[b, c],  s(r)=max(r-4,0)
// wb(r) = r*8192 - tri(r) - s(r), tri(r) = (r-5)(r-4)/2 for r>=5 else 0.
//
// Round-4 scheme:
//  k1: smem-tiled transpose x -> xT[col][b]  (coalesced, conflict-free)
//  k2: warp = (q, h): rows {4q..4q+3} (tops) + {8188-4q..8191-4q} (bottoms),
//      column 128-blocks k with k % 4 == h.  cnt(top)+cnt(bottom) is constant
//      => 4096 perfectly uniform warps (1024 blocks x 128 thr).
//      8 rows share each 32B xT fetch; accumulators packed 2-wide via
//      fma.rn.f32x2.  Guard blocks peeled (<=1 guarded iter per phase).
//  k3: out = sum_h partial[h] + bias (flip folded), float4.

constexpr int N = 8192;
constexpr int BATCH = 8;
constexpr int HS = 4;                      // column split ways

__device__ __align__(16) float g_xT[N * BATCH];        // xT[col*8 + b]
__device__ __align__(16) float g_partial[HS][BATCH][N]; // [h][b][flipped col]

// ---- packed fp32x2 helpers (Blackwell) ----
__device__ __forceinline__ unsigned long long splat2(float v) {
    unsigned long long r;
    asm("mov.b64 %0, {%1, %1};" : "=l"(r) : "f"(v));
    return r;
}
__device__ __forceinline__ void pfma(unsigned long long& d,
                                     unsigned long long a, unsigned long long b) {
    asm("fma.rn.f32x2 %0, %1, %2, %0;" : "+l"(d) : "l"(a), "l"(b));
}
__device__ __forceinline__ float2 unpack2(unsigned long long v) {
    float2 f;
    asm("mov.b64 {%0, %1}, %2;" : "=f"(f.x), "=f"(f.y) : "l"(v));
    return f;
}

// ---------------- kernel 1: tiled x transpose ----------------
__global__ __launch_bounds__(128)
void transpose_x_kernel(const float* __restrict__ x)
{
    __shared__ float s[BATCH][132];        // pad: stride 132 -> banks 4b+col, all distinct
    const int t  = threadIdx.x;            // 0..127
    const int c0 = blockIdx.x * 128;
#pragma unroll
    for (int b = 0; b < BATCH; b++)
        s[b][t] = __ldg(x + b * N + c0 + t);
    __syncthreads();
#pragma unroll
    for (int kk = 0; kk < 8; kk++) {
        const int j   = kk * 128 + t;      // 0..1023
        const int col = j >> 3;
        const int b   = j & 7;
        g_xT[c0 * BATCH + j] = s[b][col];
    }
}

// ---------------- main block body ----------------
// GT: guard top rows, BOT: bottoms active, GB: guard bottom rows
template<bool GT, bool BOT, bool GB>
__device__ __forceinline__ void do_block(
    int c, int lane, const float* __restrict__ w,
    const int* st, const int* wbT, const int* sb, const int* wbB,
    unsigned long long accT[4][4], unsigned long long accB[4][4])
{
#pragma unroll
    for (int j = 0; j < 4; j++) {
        const int col = c + lane + 32 * j;
        const ulonglong2* xp = (const ulonglong2*)(g_xT + col * BATCH);
        const ulonglong2 lo = __ldg(xp);
        const ulonglong2 hi = __ldg(xp + 1);
        unsigned long long xv[4] = { lo.x, lo.y, hi.x, hi.y };

#pragma unroll
        for (int i = 0; i < 4; i++) {
            float wv = __ldcs(w + wbT[i] + col);
            if (GT) wv = (col >= st[i]) ? wv : 0.0f;
            const unsigned long long ws = splat2(wv);
            pfma(accT[i][0], ws, xv[0]);
            pfma(accT[i][1], ws, xv[1]);
            pfma(accT[i][2], ws, xv[2]);
            pfma(accT[i][3], ws, xv[3]);
        }
        if (BOT) {
#pragma unroll
            for (int i = 0; i < 4; i++) {
                float wv = __ldcs(w + wbB[i] + col);
                if (GB) wv = (col >= sb[i]) ? wv : 0.0f;
                const unsigned long long ws = splat2(wv);
                pfma(accB[i][0], ws, xv[0]);
                pfma(accB[i][1], ws, xv[1]);
                pfma(accB[i][2], ws, xv[2]);
                pfma(accB[i][3], ws, xv[3]);
            }
        }
    }
}

// ---------------- kernel 2: triangular matvec ----------------
__global__ __launch_bounds__(128)
void tri_main_kernel(const float* __restrict__ w)
{
    const int lane = threadIdx.x & 31;
    const int wid  = threadIdx.x >> 5;
    const int gw   = blockIdx.x * 4 + wid;   // 0..4095
    const int q    = gw >> 2;                // row group 0..1023
    const int h    = gw & 3;                 // column-block residue

    int st[4], sb[4], wbT[4], wbB[4];
#pragma unroll
    for (int i = 0; i < 4; i++) {
        const int rt = 4 * q + i;
        const int rb = 8188 - 4 * q + i;
        const int s_t = (rt - 4 > 0) ? (rt - 4) : 0;
        const int s_b = rb - 4;                       // rb >= 4096 always
        const int triT = (rt >= 5) ? ((rt - 5) * (rt - 4)) / 2 : 0;
        const int triB = ((rb - 5) * (rb - 4)) / 2;
        st[i] = s_t;  sb[i] = s_b;
        wbT[i] = rt * N - triT - s_t;
        wbB[i] = rb * N - triB - s_b;
    }

    unsigned long long accT[4][4], accB[4][4];
#pragma unroll
    for (int i = 0; i < 4; i++)
#pragma unroll
        for (int kk = 0; kk < 4; kk++) { accT[i][kk] = 0ull; accB[i][kk] = 0ull; }

    const int kTopFirst = st[0] >> 7;
    const int kTopLast  = st[3] >> 7;
    const int kBotFirst = sb[0] >> 7;
    const int kBotLast  = sb[3] >> 7;

    int k = kTopFirst + ((h - kTopFirst) & 3);   // first block of residue h

    // ---- Phase A: tops only ----
    if (k <= kTopLast && k < kBotFirst) {
        do_block<true, false, false>(k << 7, lane, w, st, wbT, sb, wbB, accT, accB);
        k += 4;
    }
    for (; k < kBotFirst; k += 4)
        do_block<false, false, false>(k << 7, lane, w, st, wbT, sb, wbB, accT, accB);
    // after this loop, k is the first residue-h block >= kBotFirst

    // ---- Phase B: all 8 rows ----
    if (k < 64 && k <= kBotLast) {
        // guard everything (covers the q~1023 corner where top guards land here)
        do_block<true, true, true>(k << 7, lane, w, st, wbT, sb, wbB, accT, accB);
        k += 4;
    }
    for (; k < 64; k += 4)
        do_block<false, true, false>(k << 7, lane, w, st, wbT, sb, wbB, accT, accB);

    // ---- lane-reduce, store partials (pre-flipped) ----
#pragma unroll
    for (int i = 0; i < 4; i++) {
        const int rowT = 4 * q + i;
        const int rowB = 8188 - 4 * q + i;
#pragma unroll
        for (int kk = 0; kk < 4; kk++) {
            float2 t2 = unpack2(accT[i][kk]);
            float2 b2 = unpack2(accB[i][kk]);
            float v0 = t2.x, v1 = t2.y, v2 = b2.x, v3 = b2.y;
#pragma unroll
            for (int m = 16; m >= 1; m >>= 1) {
                v0 += __shfl_xor_sync(0xffffffffu, v0, m);
                v1 += __shfl_xor_sync(0xffffffffu, v1, m);
                v2 += __shfl_xor_sync(0xffffffffu, v2, m);
                v3 += __shfl_xor_sync(0xffffffffu, v3, m);
            }
            if (lane == 0) {
                g_partial[h][2 * kk + 0][N - 1 - rowT] = v0;
                g_partial[h][2 * kk + 1][N - 1 - rowT] = v1;
                g_partial[h][2 * kk + 0][N - 1 - rowB] = v2;
                g_partial[h][2 * kk + 1][N - 1 - rowB] = v3;
            }
        }
    }
}

// ---------------- kernel 3: combine + bias (flip folded) ----------------
__global__ __launch_bounds__(256)
void reduce_out_kernel(const float* __restrict__ bias, float* __restrict__ out)
{
    const int idx = blockIdx.x * blockDim.x + threadIdx.x;  // 0..16383 (float4 units)
    const int b  = idx >> 11;            // 2048 quads per batch row
    const int j  = (idx & 2047) << 2;    // flipped output column
    float4 a0 = *(const float4*)&g_partial[0][b][j];
    float4 a1 = *(const float4*)&g_partial[1][b][j];
    float4 a2 = *(const float4*)&g_partial[2][b][j];
    float4 a3 = *(const float4*)&g_partial[3][b][j];
    float4 r;
    r.x = a0.x + a1.x + a2.x + a3.x + __ldg(bias + (N - 1 - j));
    r.y = a0.y + a1.y + a2.y + a3.y + __ldg(bias + (N - 2 - j));
    r.z = a0.z + a1.z + a2.z + a3.z + __ldg(bias + (N - 3 - j));
    r.w = a0.w + a1.w + a2.w + a3.w + __ldg(bias + (N - 4 - j));
    ((float4*)out)[idx] = r;
}

extern "C" void kernel_launch(void* const* d_in, const int* in_sizes, int n_in,
                              void* d_out, int out_size)
{
    const float* x    = (const float*)d_in[0];   // [8, 8192] fp32
    const float* w    = (const float*)d_in[1];   // packed weights fp32
    const float* bias = (const float*)d_in[2];   // [8192] fp32
    float* out        = (float*)d_out;           // [8, 8192] fp32

    transpose_x_kernel<<<64, 128>>>(x);
    tri_main_kernel<<<1024, 128>>>(w);           // 4096 uniform warps
    reduce_out_kernel<<<64, 256>>>(bias, out);
}

// round 6
// speedup vs baseline: 2.5078x; 1.1990x over previous
#include <cuda_runtime.h>

// TriangleLinear on GB300 (sm_103a).
// out[b, 8191-r] = bias[r] + sum_{c >= s(r)} W[wb(r) + c] * x[b, c],  s(r)=max(r-4,0)
// wb(r) = r*8192 - tri(r) - s(r), tri(r) = (r-5)(r-4)/2 for r>=5 else 0.
//
// Round-5 scheme:
//  k1: parallel smem-tiled transpose x -> xT[col][b] (65536 threads, 1 ld/st each)
//  k2: block = (Q, h): 8 warps, warp wid handles row-group q = 8Q + wid
//      (rows 4q..4q+3 + mirror rows), column 128-blocks k with k % 4 == h.
//      All 8 warps share the SAME h => identical xT stream => L1 hits.
//      x loads hoisted & front-batched per block; w loads batched per j.
//      Accumulators packed 2-wide (fma.rn.f32x2). Guard blocks peeled.
//  k3: out = sum_h partial[h] + bias (flip folded), float4.

constexpr int N = 8192;
constexpr int BATCH = 8;
constexpr int HS = 4;

__device__ __align__(16) float g_xT[N * BATCH];          // xT[col*8 + b]
__device__ __align__(16) float g_partial[HS][BATCH][N];  // [h][b][flipped col]

// ---- packed fp32x2 helpers (Blackwell) ----
__device__ __forceinline__ unsigned long long splat2(float v) {
    unsigned long long r;
    asm("mov.b64 %0, {%1, %1};" : "=l"(r) : "f"(v));
    return r;
}
__device__ __forceinline__ void pfma(unsigned long long& d,
                                     unsigned long long a, unsigned long long b) {
    asm("fma.rn.f32x2 %0, %1, %2, %0;" : "+l"(d) : "l"(a), "l"(b));
}
__device__ __forceinline__ float2 unpack2(unsigned long long v) {
    float2 f;
    asm("mov.b64 {%0, %1}, %2;" : "=f"(f.x), "=f"(f.y) : "l"(v));
    return f;
}

// ---------------- kernel 1: parallel tiled transpose ----------------
__global__ __launch_bounds__(256)
void transpose_x_kernel(const float* __restrict__ x)
{
    __shared__ float s[BATCH][36];          // pad 36: 4b+c banks, all distinct
    const int t  = threadIdx.x;             // 0..255
    const int c0 = blockIdx.x * 32;         // 32-col tile
    // load: thread t -> b = t>>5, col = t&31 (coalesced 128B per row)
    s[t >> 5][t & 31] = __ldg(x + (t >> 5) * N + c0 + (t & 31));
    __syncthreads();
    // store: thread t -> col = t>>3, b = t&7 (fully coalesced)
    g_xT[c0 * BATCH + t] = s[t & 7][t >> 3];
}

// ---------------- main block body ----------------
// GT: guard top rows, BOT: bottoms active, GB: guard bottom rows
template<bool GT, bool BOT, bool GB>
__device__ __forceinline__ void do_block(
    int c, int lane, const float* __restrict__ w,
    const int* st, const int* wbT, const int* sb, const int* wbB,
    unsigned long long accT[4][4], unsigned long long accB[4][4])
{
    // front-batch ALL x loads for this 128-col block (8 x LDG.128)
    unsigned long long xv[4][4];
#pragma unroll
    for (int j = 0; j < 4; j++) {
        const int col = c + lane + 32 * j;
        const ulonglong2* xp = (const ulonglong2*)(g_xT + col * BATCH);
        const ulonglong2 lo = __ldg(xp);
        const ulonglong2 hi = __ldg(xp + 1);
        xv[j][0] = lo.x; xv[j][1] = lo.y; xv[j][2] = hi.x; xv[j][3] = hi.y;
    }

#pragma unroll
    for (int j = 0; j < 4; j++) {
        const int col = c + lane + 32 * j;
        // batch the w loads for this j before any FMA
        float wvT[4], wvB[4];
#pragma unroll
        for (int i = 0; i < 4; i++) {
            wvT[i] = __ldcs(w + wbT[i] + col);
            if (GT) wvT[i] = (col >= st[i]) ? wvT[i] : 0.0f;
        }
        if (BOT) {
#pragma unroll
            for (int i = 0; i < 4; i++) {
                wvB[i] = __ldcs(w + wbB[i] + col);
                if (GB) wvB[i] = (col >= sb[i]) ? wvB[i] : 0.0f;
            }
        }
#pragma unroll
        for (int i = 0; i < 4; i++) {
            const unsigned long long ws = splat2(wvT[i]);
            pfma(accT[i][0], ws, xv[j][0]);
            pfma(accT[i][1], ws, xv[j][1]);
            pfma(accT[i][2], ws, xv[j][2]);
            pfma(accT[i][3], ws, xv[j][3]);
        }
        if (BOT) {
#pragma unroll
            for (int i = 0; i < 4; i++) {
                const unsigned long long ws = splat2(wvB[i]);
                pfma(accB[i][0], ws, xv[j][0]);
                pfma(accB[i][1], ws, xv[j][1]);
                pfma(accB[i][2], ws, xv[j][2]);
                pfma(accB[i][3], ws, xv[j][3]);
            }
        }
    }
}

// ---------------- kernel 2: triangular matvec ----------------
__global__ __launch_bounds__(256, 2)
void tri_main_kernel(const float* __restrict__ w)
{
    const int lane = threadIdx.x & 31;
    const int wid  = threadIdx.x >> 5;        // 0..7
    const int h    = blockIdx.x & 3;          // shared by all 8 warps of the block
    const int q    = (blockIdx.x >> 2) * 8 + wid;   // 0..1023

    int st[4], sb[4], wbT[4], wbB[4];
#pragma unroll
    for (int i = 0; i < 4; i++) {
        const int rt = 4 * q + i;
        const int rb = 8188 - 4 * q + i;
        const int s_t = (rt - 4 > 0) ? (rt - 4) : 0;
        const int s_b = rb - 4;                      // rb >= 4096 always
        const int triT = (rt >= 5) ? ((rt - 5) * (rt - 4)) / 2 : 0;
        const int triB = ((rb - 5) * (rb - 4)) / 2;
        st[i] = s_t;  sb[i] = s_b;
        wbT[i] = rt * N - triT - s_t;
        wbB[i] = rb * N - triB - s_b;
    }

    unsigned long long accT[4][4], accB[4][4];
#pragma unroll
    for (int i = 0; i < 4; i++)
#pragma unroll
        for (int kk = 0; kk < 4; kk++) { accT[i][kk] = 0ull; accB[i][kk] = 0ull; }

    const int kTopFirst = st[0] >> 7;
    const int kTopLast  = st[3] >> 7;
    const int kBotFirst = sb[0] >> 7;
    const int kBotLast  = sb[3] >> 7;

    int k = kTopFirst + ((h - kTopFirst) & 3);   // first block of residue h

    // ---- Phase A: tops only ----
    if (k <= kTopLast && k < kBotFirst) {
        do_block<true, false, false>(k << 7, lane, w, st, wbT, sb, wbB, accT, accB);
        k += 4;
    }
    for (; k < kBotFirst; k += 4)
        do_block<false, false, false>(k << 7, lane, w, st, wbT, sb, wbB, accT, accB);

    // ---- Phase B: all 8 rows ----
    if (k < 64 && k <= kBotLast) {
        do_block<true, true, true>(k << 7, lane, w, st, wbT, sb, wbB, accT, accB);
        k += 4;
    }
    for (; k < 64; k += 4)
        do_block<false, true, false>(k << 7, lane, w, st, wbT, sb, wbB, accT, accB);

    // ---- lane-reduce, store partials (pre-flipped) ----
#pragma unroll
    for (int i = 0; i < 4; i++) {
        const int rowT = 4 * q + i;
        const int rowB = 8188 - 4 * q + i;
#pragma unroll
        for (int kk = 0; kk < 4; kk++) {
            float2 t2 = unpack2(accT[i][kk]);
            float2 b2 = unpack2(accB[i][kk]);
            float v0 = t2.x, v1 = t2.y, v2 = b2.x, v3 = b2.y;
#pragma unroll
            for (int m = 16; m >= 1; m >>= 1) {
                v0 += __shfl_xor_sync(0xffffffffu, v0, m);
                v1 += __shfl_xor_sync(0xffffffffu, v1, m);
                v2 += __shfl_xor_sync(0xffffffffu, v2, m);
                v3 += __shfl_xor_sync(0xffffffffu, v3, m);
            }
            if (lane == 0) {
                g_partial[h][2 * kk + 0][N - 1 - rowT] = v0;
                g_partial[h][2 * kk + 1][N - 1 - rowT] = v1;
                g_partial[h][2 * kk + 0][N - 1 - rowB] = v2;
                g_partial[h][2 * kk + 1][N - 1 - rowB] = v3;
            }
        }
    }
}

// ---------------- kernel 3: combine + bias (flip folded) ----------------
__global__ __launch_bounds__(256)
void reduce_out_kernel(const float* __restrict__ bias, float* __restrict__ out)
{
    const int idx = blockIdx.x * blockDim.x + threadIdx.x;  // 0..16383 (float4 units)
    const int b  = idx >> 11;
    const int j  = (idx & 2047) << 2;
    float4 a0 = *(const float4*)&g_partial[0][b][j];
    float4 a1 = *(const float4*)&g_partial[1][b][j];
    float4 a2 = *(const float4*)&g_partial[2][b][j];
    float4 a3 = *(const float4*)&g_partial[3][b][j];
    float4 r;
    r.x = a0.x + a1.x + a2.x + a3.x + __ldg(bias + (N - 1 - j));
    r.y = a0.y + a1.y + a2.y + a3.y + __ldg(bias + (N - 2 - j));
    r.z = a0.z + a1.z + a2.z + a3.z + __ldg(bias + (N - 3 - j));
    r.w = a0.w + a1.w + a2.w + a3.w + __ldg(bias + (N - 4 - j));
    ((float4*)out)[idx] = r;
}

extern "C" void kernel_launch(void* const* d_in, const int* in_sizes, int n_in,
                              void* d_out, int out_size)
{
    const float* x    = (const float*)d_in[0];   // [8, 8192] fp32
    const float* w    = (const float*)d_in[1];   // packed weights fp32
    const float* bias = (const float*)d_in[2];   // [8192] fp32
    float* out        = (float*)d_out;           // [8, 8192] fp32

    transpose_x_kernel<<<256, 256>>>(x);         // 65536 threads, 1 ld/st each
    tri_main_kernel<<<512, 256>>>(w);            // 4096 uniform warps, h-shared blocks
    reduce_out_kernel<<<64, 256>>>(bias, out);
}